// round 4
// baseline (speedup 1.0000x reference)
#include <cuda_runtime.h>
#include <cstdint>

#define PI_F 3.14159265358979323846f
static __device__ float2 g_A[33554432];   // forward spectrum (x<=128 cols valid)
static __device__ float2 g_B[33554432];   // inverse pipeline
static __device__ float2 g_C[16777216];   // 2x2-averaged planes: [b][izu<128][jy][jx]

__device__ __forceinline__ float2 cmul(float2 a, float2 b){
    return make_float2(a.x*b.x - a.y*b.y, a.x*b.y + a.y*b.x);
}
// base-4 digit reversal of an 8-bit index
__device__ __forceinline__ int drev4(int i){
    return ((i & 3) << 6) | (((i >> 2) & 3) << 4) | (((i >> 4) & 3) << 2) | ((i >> 6) & 3);
}

// First NSTAGES stages (L=1,4,16,...) of a 256-pt radix-4 DIT FFT in shared.
// Input stored drev4-ordered. NT threads per line.
template<int SIGN, int NT, int NSTAGES>
__device__ __forceinline__ void fft256_r4s(float2* s, int t){
#pragma unroll
    for (int st = 0; st < NSTAGES; ++st){
        int L = 1 << (2*st);
        __syncthreads();
#pragma unroll
        for (int k = 0; k < 64/NT; ++k){
            int j = t + k*NT;
            int p = j & (L - 1);
            int base = ((j >> (2*st)) << (2*st + 2)) + p;
            float ang = (float)SIGN * (2.0f*PI_F) * (float)p / (float)(4*L);
            float sn, cs; __sincosf(ang, &sn, &cs);
            float2 w1 = make_float2(cs, sn);
            float2 w2 = make_float2(cs*cs - sn*sn, 2.0f*cs*sn);
            float2 w3 = cmul(w1, w2);
            float2 a0 = s[base];
            float2 a1 = cmul(w1, s[base + L]);
            float2 a2 = cmul(w2, s[base + 2*L]);
            float2 a3 = cmul(w3, s[base + 3*L]);
            float2 t02p = make_float2(a0.x + a2.x, a0.y + a2.y);
            float2 t02m = make_float2(a0.x - a2.x, a0.y - a2.y);
            float2 t13p = make_float2(a1.x + a3.x, a1.y + a3.y);
            float2 t13m = make_float2(a1.x - a3.x, a1.y - a3.y);
            float2 jt = (SIGN < 0) ? make_float2(t13m.y, -t13m.x)
                                   : make_float2(-t13m.y, t13m.x);
            s[base]       = make_float2(t02p.x + t13p.x, t02p.y + t13p.y);
            s[base + L]   = make_float2(t02m.x + jt.x,   t02m.y + jt.y);
            s[base + 2*L] = make_float2(t02p.x - t13p.x, t02p.y - t13p.y);
            s[base + 3*L] = make_float2(t02m.x - jt.x,   t02m.y - jt.y);
        }
    }
    __syncthreads();
}

// Last stage (L=64) computed in registers from shared. Butterfly j in [0,64).
// Outputs land at natural indices j, j+64, j+128, j+192.
template<int SIGN>
__device__ __forceinline__ void fft256_last(const float2* s, int j,
        float2& o0, float2& o1, float2& o2, float2& o3){
    float ang = (float)SIGN * (2.0f*PI_F) * (float)j * (1.0f/256.0f);
    float sn, cs; __sincosf(ang, &sn, &cs);
    float2 w1 = make_float2(cs, sn);
    float2 w2 = make_float2(cs*cs - sn*sn, 2.0f*cs*sn);
    float2 w3 = cmul(w1, w2);
    float2 a0 = s[j];
    float2 a1 = cmul(w1, s[j + 64]);
    float2 a2 = cmul(w2, s[j + 128]);
    float2 a3 = cmul(w3, s[j + 192]);
    float2 t02p = make_float2(a0.x + a2.x, a0.y + a2.y);
    float2 t02m = make_float2(a0.x - a2.x, a0.y - a2.y);
    float2 t13p = make_float2(a1.x + a3.x, a1.y + a3.y);
    float2 t13m = make_float2(a1.x - a3.x, a1.y - a3.y);
    float2 jt = (SIGN < 0) ? make_float2(t13m.y, -t13m.x)
                           : make_float2(-t13m.y, t13m.x);
    o0 = make_float2(t02p.x + t13p.x, t02p.y + t13p.y);
    o1 = make_float2(t02m.x + jt.x,   t02m.y + jt.y);
    o2 = make_float2(t02p.x - t13p.x, t02p.y - t13p.y);
    o3 = make_float2(t02m.x - jt.x,   t02m.y - jt.y);
}

// Forward X + prep: v = sqrt(relu(in*(z/127)^2)), pad to 256, store x<=128 only.
// Block: 2 lines x 64 threads.
__global__ void k_fwd_x(const float* __restrict__ in){
    __shared__ float2 s[2*256];
    int tid = threadIdx.x;
    int l = tid >> 6, t = tid & 63;
    int y = (blockIdx.x << 1) + l;
    int zz = blockIdx.y, b = blockIdx.z;
    float g = (float)zz * (1.0f/127.0f);
    float g2 = g*g;
    const float* row = in + (((size_t)b*128 + zz)*128 + y)*128;
    float2* sl = s + (l << 8);
#pragma unroll
    for (int k = 0; k < 4; ++k){
        int j = t + (k << 6);
        int src = drev4(j);
        float v = 0.0f;
        if (src < 128) v = sqrtf(fmaxf(row[src]*g2, 0.0f));
        sl[j] = make_float2(v, 0.0f);
    }
    fft256_r4s<-1,64,3>(sl, t);
    float2 o0,o1,o2,o3;
    fft256_last<-1>(sl, t, o0,o1,o2,o3);
    float2* outl = g_A + (((size_t)b*256 + zz)*256 + y)*256;
    outl[t]      = o0;
    outl[t + 64] = o1;
    if (t == 0) outl[128] = o2;
}

// Forward Y: x columns [0,128]. Read y<128 (zero-pad), write all 256 y.
// Block: 16 x-lanes x 16 threads.
__global__ void k_fwd_y(){
    __shared__ float2 s[16*257];
    int x0 = blockIdx.x << 4, zz = blockIdx.y, b = blockIdx.z;
    int tid = threadIdx.x, xl = tid & 15, u = tid >> 4;
    bool valid = (x0 + xl) <= 128;
    float2* base = g_A + ((size_t)b << 24) + ((size_t)zz << 16) + x0;
    float2* sl = s + xl*257;
#pragma unroll
    for (int c = 0; c < 8; ++c){
        int yy = (c << 4) + u;
        float2 v = make_float2(0.f, 0.f);
        if (valid) v = base[(size_t)yy*256 + xl];
        sl[drev4(yy)]       = v;
        sl[drev4(yy + 128)] = make_float2(0.f, 0.f);
    }
    fft256_r4s<-1,16,3>(sl, u);
    if (valid){
#pragma unroll
        for (int k = 0; k < 4; ++k){
            int j = (k << 4) + u;
            float2 o0,o1,o2,o3;
            fft256_last<-1>(sl, j, o0,o1,o2,o3);
            base[(size_t)j*256 + xl]         = o0;
            base[(size_t)(j + 64)*256 + xl]  = o1;
            base[(size_t)(j + 128)*256 + xl] = o2;
            base[(size_t)(j + 192)*256 + xl] = o3;
        }
    }
}

// Forward Z: x columns [0,128]. Read z<128 (zero-pad), write all 256 z.
__global__ void k_fwd_z(){
    __shared__ float2 s[16*257];
    int x0 = blockIdx.x << 4, y = blockIdx.y, b = blockIdx.z;
    int tid = threadIdx.x, xl = tid & 15, u = tid >> 4;
    bool valid = (x0 + xl) <= 128;
    float2* base = g_A + ((size_t)b << 24) + ((size_t)y << 8) + x0;
    float2* sl = s + xl*257;
#pragma unroll
    for (int c = 0; c < 8; ++c){
        int zz = (c << 4) + u;
        float2 v = make_float2(0.f, 0.f);
        if (valid) v = base[(size_t)zz*65536 + xl];
        sl[drev4(zz)]       = v;
        sl[drev4(zz + 128)] = make_float2(0.f, 0.f);
    }
    fft256_r4s<-1,16,3>(sl, u);
    if (valid){
#pragma unroll
        for (int k = 0; k < 4; ++k){
            int j = (k << 4) + u;
            float2 o0,o1,o2,o3;
            fft256_last<-1>(sl, j, o0,o1,o2,o3);
            base[(size_t)j*65536 + xl]         = o0;
            base[(size_t)(j + 64)*65536 + xl]  = o1;
            base[(size_t)(j + 128)*65536 + xl] = o2;
            base[(size_t)(j + 192)*65536 + xl] = o3;
        }
    }
}

// Precompute 0.25 * 2x2 x/y stencil (with Hermitian conj reconstruction and
// boundary zeros) for the 128 z-planes the resample can touch.
// C[b][izu][jy][jx], laid out in resample's output coordinates (coalesced reads).
__global__ void k_avg(){
    int jx = threadIdx.x;           // 0..255
    int jy = blockIdx.x;            // 0..255
    int izu = blockIdx.y;           // 0..127  (iz = izu + 128 in shifted coords)
    int b = blockIdx.z;
    int sy = jy ^ 128, sx = jx ^ 128;
    int izn = (256 - izu) & 255;
    const float2* Ab = g_A + ((size_t)b << 24);
    float acx = 0.f, acy = 0.f;
#pragma unroll
    for (int ty = 0; ty < 2; ++ty){
        int iy = sy - 1 + ty;
        if (iy < 0) continue;
        int iyu = iy ^ 128;
        int iyn = (256 - iyu) & 255;
#pragma unroll
        for (int tx = 0; tx < 2; ++tx){
            int ix = sx - 1 + tx;
            if (ix < 0) continue;
            int ixu = ix ^ 128;
            float2 v;
            if (ixu <= 128){
                v = __ldg(&Ab[((size_t)izu << 16) + ((size_t)iyu << 8) + (size_t)ixu]);
                acx += v.x; acy += v.y;
            } else {
                v = __ldg(&Ab[((size_t)izn << 16) + ((size_t)iyn << 8) + (size_t)(256 - ixu)]);
                acx += v.x; acy -= v.y;     // conjugate
            }
        }
    }
    g_C[((size_t)b << 23) + ((size_t)izu << 16) + ((size_t)jy << 8) + (size_t)jx]
        = make_float2(acx * 0.25f, acy * 0.25f);
}

// Fused Stolt z-interp + inverse X FFT. 2 coalesced loads per sample from g_C.
// Block: 4 jy-lines x 64 threads; each thread 4 samples.
__global__ void k_resample_invx(){
    __shared__ float2 s[4*256];
    int tid = threadIdx.x;
    int line = tid >> 6, t = tid & 63;
    int jy = (blockIdx.x << 2) + line;
    int jz = blockIdx.y + 1;        // 1..127
    int b  = blockIdx.z;
    int sy = jy ^ 128;
    float gz = (float)jz * (1.0f/128.0f);
    float gy = (float)(sy - 128) * (1.0f/128.0f);
    const float fk = 0.1024f;
    float gyz = fk*gy*gy + gz*gz;
    const float2* Cb = g_C + ((size_t)b << 23) + ((size_t)jy << 8);
    float2* sl = s + (line << 8);
#pragma unroll
    for (int k = 0; k < 4; ++k){
        int jx = t + (k << 6);
        int sx = jx ^ 128;
        float gx = (float)(sx - 128) * (1.0f/128.0f);
        float gznew = sqrtf(fk*gx*gx + gyz);
        float pz = (gznew + 1.0f)*128.0f - 0.5f;    // >= 128.5
        float z0f = floorf(pz);
        float dz = pz - z0f;
        int z0u = (int)z0f - 128;                   // >= 0
        float2 c0 = make_float2(0.f, 0.f), c1 = make_float2(0.f, 0.f);
        if (z0u <= 127) c0 = __ldg(&Cb[((size_t)z0u << 16) + (size_t)jx]);
        if (z0u <= 126) c1 = __ldg(&Cb[((size_t)(z0u + 1) << 16) + (size_t)jx]);
        float w0 = 1.0f - dz;
        float fac = gz / (gznew + 1e-8f) * (1.0f/256.0f);
        sl[drev4(jx)] = make_float2((w0*c0.x + dz*c1.x) * fac,
                                    (w0*c0.y + dz*c1.y) * fac);
    }
    fft256_r4s<1,64,3>(sl, t);
    float2 o0,o1,o2,o3;
    fft256_last<1>(sl, t, o0,o1,o2,o3);
    size_t o = ((size_t)b << 24) + ((size_t)jz << 16) + ((size_t)jy << 8);
    g_B[o + t]      = o0;
    g_B[o + t + 64] = o1;
}

// Inverse Y: lines (b, z in [1,128), x<128). Read all y, write y<128 (scaled).
__global__ void k_inv_y(){
    __shared__ float2 s[16*257];
    int x0 = blockIdx.x << 4, zz = blockIdx.y + 1, b = blockIdx.z;
    int tid = threadIdx.x, xl = tid & 15, u = tid >> 4;
    float2* base = g_B + ((size_t)b << 24) + ((size_t)zz << 16) + x0;
    float2* sl = s + xl*257;
#pragma unroll
    for (int c = 0; c < 16; ++c){
        int yy = (c << 4) + u;
        sl[drev4(yy)] = base[(size_t)yy*256 + xl];
    }
    fft256_r4s<1,16,3>(sl, u);
#pragma unroll
    for (int k = 0; k < 4; ++k){
        int j = (k << 4) + u;               // < 64
        float2 o0,o1,o2,o3;
        fft256_last<1>(sl, j, o0,o1,o2,o3);
        base[(size_t)j*256 + xl]        = make_float2(o0.x*(1.f/256.f), o0.y*(1.f/256.f));
        base[(size_t)(j + 64)*256 + xl] = make_float2(o1.x*(1.f/256.f), o1.y*(1.f/256.f));
    }
}

// Inverse Z: lines (b, y<128, x<128). Only z in [1,128) nonzero.
// Write Re(z<128) * 1/256 straight to output.
__global__ void k_inv_z(float* __restrict__ out){
    __shared__ float2 s[16*257];
    int x0 = blockIdx.x << 4, y = blockIdx.y, b = blockIdx.z;
    int tid = threadIdx.x, xl = tid & 15, u = tid >> 4;
    const float2* base = g_B + ((size_t)b << 24) + ((size_t)y << 8) + x0;
    float2* sl = s + xl*257;
#pragma unroll
    for (int c = 0; c < 8; ++c){
        int zz = (c << 4) + u;                  // 0..127
        float2 v = make_float2(0.f, 0.f);
        if (zz >= 1) v = base[(size_t)zz*65536 + xl];
        sl[drev4(zz)]       = v;
        sl[drev4(zz + 128)] = make_float2(0.f, 0.f);
    }
    fft256_r4s<1,16,3>(sl, u);
    float* outb = out + ((size_t)b*128*128*128) + (size_t)y*128 + (size_t)(x0 + xl);
#pragma unroll
    for (int k = 0; k < 4; ++k){
        int j = (k << 4) + u;               // < 64
        float2 o0,o1,o2,o3;
        fft256_last<1>(sl, j, o0,o1,o2,o3);
        outb[(size_t)j*16384]        = o0.x * (1.f/256.f);
        outb[(size_t)(j + 64)*16384] = o1.x * (1.f/256.f);
    }
}

extern "C" void kernel_launch(void* const* d_in, const int* in_sizes, int n_in,
                              void* d_out, int out_size){
    (void)in_sizes; (void)n_in; (void)out_size;
    const float* in = (const float*)d_in[0];
    float* out = (float*)d_out;

    k_fwd_x        <<<dim3(64,  128, 2), 128>>>(in);
    k_fwd_y        <<<dim3(9,   128, 2), 256>>>();
    k_fwd_z        <<<dim3(9,   256, 2), 256>>>();
    k_avg          <<<dim3(256, 128, 2), 256>>>();
    k_resample_invx<<<dim3(64,  127, 2), 256>>>();
    k_inv_y        <<<dim3(8,   127, 2), 256>>>();
    k_inv_z        <<<dim3(8,   128, 2), 256>>>(out);
}